// round 11
// baseline (speedup 1.0000x reference)
#include <cuda_runtime.h>
#include <cuda_fp16.h>
#include <cstdint>

#define EPS 1e-5f
#define RD 6            // smem ring depth (chunks of 32KB)

// ---------------- device globals (scratch; no allocations allowed) ----------------
// packed recurrent weights: [m][b][r][k=512][rowlocal=256] fp16 ; m=0: whh0, m=1: wih1+whh1
__device__ __half g_warr[2u * 16u * 8u * 512u * 256u];                 // 67.1 MB
__device__ float g_gi0[16u * 256u * 2048u];                            // 33.5 MB: wih0@x + bias0
__device__ float g_bias0[16u * 2048u];
__device__ float g_bias1[16u * 2048u];
__device__ float2 g_stat[16u * 8u * 4u];                               // gate stats: [b][rank][gate]
__device__ unsigned g_tag1[16u * 8u * 4u];                             // per (b,rank,gate) phase tag
__device__ float2 g_co[16u * 512u];                                    // (c, o) pairs: [b][j]
__device__ unsigned g_tag2[16u * 8u];                                  // per (b,rank) phase tag
__device__ float g_dummy;

// ---------------- helpers ----------------
__device__ __forceinline__ uint32_t smem_u32(const void* p) {
    uint32_t a;
    asm("{ .reg .u64 t; cvta.to.shared.u64 t, %1; cvt.u32.u64 %0, t; }" : "=r"(a) : "l"(p));
    return a;
}
__device__ __forceinline__ void cpa16(uint32_t dst, const void* src) {
    asm volatile("cp.async.cg.shared.global [%0], [%1], 16;" :: "r"(dst), "l"(src) : "memory");
}
__device__ __forceinline__ void st_rel_u32(unsigned* p, unsigned v) {
    asm volatile("st.release.gpu.global.u32 [%0], %1;" :: "l"(p), "r"(v) : "memory");
}
__device__ __forceinline__ unsigned ld_acq_u32(const unsigned* p) {
    unsigned v;
    asm volatile("ld.acquire.gpu.global.u32 %0, [%1];" : "=r"(v) : "l"(p) : "memory");
    return v;
}
__device__ __forceinline__ float fast_rcp(float x) {
    float r; asm("rcp.approx.f32 %0, %1;" : "=f"(r) : "f"(x)); return r;
}
__device__ __forceinline__ float fast_sigmoid(float x) {
    return fast_rcp(1.0f + __expf(-x));
}
__device__ __forceinline__ float fast_tanh(float x) {
    float r; asm("tanh.approx.f32 %0, %1;" : "=f"(r) : "f"(x)); return r;
}

// ---------------- K0: per-launch init ----------------
__global__ void k0_init(const float* __restrict__ bih0, const float* __restrict__ bhh0,
                        const float* __restrict__ bih1, const float* __restrict__ bhh1) {
    int i = blockIdx.x * blockDim.x + threadIdx.x;   // 32768 = 16*2048
    g_bias0[i] = bih0[i] + bhh0[i];
    g_bias1[i] = bih1[i] + bhh1[i];
    if (i < 512) g_tag1[i] = 0u;
    if (i < 128) g_tag2[i] = 0u;
}

// ---------------- K1: pack/transpose recurrent weights to fp16 [k][row] ----------------
// grid (8 ktile, 8 rank, 32 = m*16+b), 256 threads; tile = 64 k x 256 rows
__global__ void k1_pack(const float* __restrict__ whh0, const float* __restrict__ wih1,
                        const float* __restrict__ whh1) {
    __shared__ __align__(16) __half sm[64 * 264];
    int kt = blockIdx.x, r = blockIdx.y;
    int mb = blockIdx.z; int m = mb >> 4, b = mb & 15;
    int tid = threadIdx.x;
    int grow = ((tid >> 6) << 9) + (r << 6) + (tid & 63);
    int k0 = kt * 64;
    const float* s0 = (m == 0 ? whh0 : wih1) + ((size_t)(b * 2048 + grow) * 512 + k0);
    const float* s1 = whh1 + ((size_t)(b * 2048 + grow) * 512 + k0);
#pragma unroll
    for (int q = 0; q < 16; q++) {
        float4 v = *(const float4*)(s0 + q * 4);
        if (m) {
            float4 u = *(const float4*)(s1 + q * 4);
            v.x += u.x; v.y += u.y; v.z += u.z; v.w += u.w;
        }
        sm[(q * 4 + 0) * 264 + tid] = __float2half(v.x);
        sm[(q * 4 + 1) * 264 + tid] = __float2half(v.y);
        sm[(q * 4 + 2) * 264 + tid] = __float2half(v.z);
        sm[(q * 4 + 3) * 264 + tid] = __float2half(v.w);
    }
    __syncthreads();
    __half* out = &g_warr[(((size_t)mb) * 8u + r) * 512u * 256u + (size_t)k0 * 256u];
    int kk = tid >> 2, rb = (tid & 3) * 64;
    const uint4* src = (const uint4*)(sm + kk * 264 + rb);
    uint4* dst = (uint4*)(out + kk * 256 + rb);
#pragma unroll
    for (int q = 0; q < 8; q++) dst[q] = src[q];
}

// ---------------- K2: precompute gi0[b][t][row] = wih0@x_t + bias0 ----------------
__global__ void k2_gemm(const float* __restrict__ wih0, const float* __restrict__ x) {
    __shared__ float As[64][17];
    __shared__ float Bs[16][65];
    int rt = blockIdx.x, tt = blockIdx.y, b = blockIdx.z;
    int row0 = rt * 64, t0 = tt * 64;
    int tid = threadIdx.x;
    int lm = tid >> 2, kq = tid & 3;
    const float* Ap = wih0 + ((size_t)(b * 2048 + row0 + lm) * 512 + kq * 4);
    const float* Bp = x + ((size_t)(b * 256 + t0 + lm) * 512 + kq * 4);
    int ty = tid >> 4, tx = tid & 15;
    float C[4][4];
#pragma unroll
    for (int i = 0; i < 4; i++)
#pragma unroll
        for (int j = 0; j < 4; j++) C[i][j] = 0.f;

    for (int kc = 0; kc < 512; kc += 16) {
        float4 a4 = *(const float4*)(Ap + kc);
        float4 b4 = *(const float4*)(Bp + kc);
        As[lm][kq * 4 + 0] = a4.x; As[lm][kq * 4 + 1] = a4.y;
        As[lm][kq * 4 + 2] = a4.z; As[lm][kq * 4 + 3] = a4.w;
        Bs[kq * 4 + 0][lm] = b4.x; Bs[kq * 4 + 1][lm] = b4.y;
        Bs[kq * 4 + 2][lm] = b4.z; Bs[kq * 4 + 3][lm] = b4.w;
        __syncthreads();
#pragma unroll
        for (int kk = 0; kk < 16; kk++) {
            float a[4], bb[4];
#pragma unroll
            for (int i = 0; i < 4; i++) a[i] = As[ty * 4 + i][kk];
#pragma unroll
            for (int j = 0; j < 4; j++) bb[j] = Bs[kk][tx * 4 + j];
#pragma unroll
            for (int i = 0; i < 4; i++)
#pragma unroll
                for (int j = 0; j < 4; j++) C[i][j] += a[i] * bb[j];
        }
        __syncthreads();
    }
    float4 bias = *(const float4*)&g_bias0[b * 2048 + row0 + ty * 4];
#pragma unroll
    for (int j = 0; j < 4; j++) {
        float4 vo;
        vo.x = C[0][j] + bias.x; vo.y = C[1][j] + bias.y;
        vo.z = C[2][j] + bias.z; vo.w = C[3][j] + bias.w;
        *(float4*)&g_gi0[((size_t)(b * 256 + t0 + tx * 4 + j)) * 2048 + row0 + ty * 4] = vo;
    }
}

// ---------------- K3: persistent recurrent kernel ----------------
// 128 CTAs x 256 threads. group g = batch, rank r owns h[64r..64r+64) + its 256 gate rows.
// Weight stream via 6-slot cp.async ring, consume-then-issue (ring always full entering
// the serial phase). Cross-CTA exchange is barrier-free: payload stores + release-tags,
// consumers poll tags with acquire loads. Tags increase monotonically (no reset races).
struct K3S {
    __half wring[RD * 64 * 256];   // 196608 B: RD chunk slots, [k64][row256]
    float h_s[512];
    float red[8][256];
    float act_s[256];
    float wpart[8][2];
    float gwf[1024], gbf[1024];    // LN params, both layers
    float bias1_s[256];
};

__global__ void __launch_bounds__(256, 1)
k3_lstm(const float* __restrict__ ln_w, const float* __restrict__ ln_b, float* __restrict__ y) {
    extern __shared__ __align__(16) unsigned char sraw[];
    K3S* S = (K3S*)sraw;

    int bid = blockIdx.x;
    int g = bid >> 3, r = bid & 7;
    int tid = threadIdx.x, warp = tid >> 5, lane = tid & 31;
    int gate = tid >> 6, jl = tid & 63;

    const uint4* Wl[2];
    Wl[0] = (const uint4*)&g_warr[(((size_t)(0 * 16 + g)) * 8u + r) * 512u * 256u];
    Wl[1] = (const uint4*)&g_warr[(((size_t)(1 * 16 + g)) * 8u + r) * 512u * 256u];
    uint32_t wring_a = smem_u32(S->wring) + (uint32_t)(warp * 256 + lane) * 16u;

    int iss_it = 0, iss_c = 0, iss_slot = 0;
#define ISSUE_CHUNK() do {                                                          \
        if (iss_it < 512) {                                                         \
            const uint4* _src = Wl[iss_it & 1] + (size_t)((iss_c * 64 + warp * 8) * 32 + lane); \
            uint32_t _dst = wring_a + (uint32_t)(iss_slot * 32768);                 \
            _Pragma("unroll")                                                       \
            for (int _i = 0; _i < 8; _i++) cpa16(_dst + _i * 512u, _src + _i * 32); \
        }                                                                           \
        asm volatile("cp.async.commit_group;" ::: "memory");                        \
        if (++iss_c == 8) { iss_c = 0; iss_it++; }                                  \
        if (++iss_slot == RD) iss_slot = 0;                                         \
    } while (0)

    // prologue: fill the whole ring (6 chunks ahead), init state
    ISSUE_CHUNK(); ISSUE_CHUNK(); ISSUE_CHUNK();
    ISSUE_CHUNK(); ISSUE_CHUNK(); ISSUE_CHUNK();
    S->h_s[tid] = 0.f; S->h_s[tid + 256] = 0.f;
    for (int i = tid; i < 1024; i += 256) { S->gwf[i] = ln_w[i]; S->gbf[i] = ln_b[i]; }
    S->bias1_s[tid] = g_bias1[g * 2048 + (gate << 9) + (r << 6) + jl];
    __syncthreads();

    float c_r = 0.f;           // cell state: thread tid<64 owns j = r*64 + tid
    unsigned tag = 0;
    int comp_slot = 0;

    for (int t = 0; t < 256; t++) {
        const float* gi0_t = &g_gi0[((size_t)(g * 256 + t)) * 2048];
        for (int l = 0; l < 2; l++) {
            tag++;

            // ---- per-row additive term (issue load early) ----
            int rowg = (gate << 9) + (r << 6) + jl;
            float gin = l ? S->bias1_s[tid] : __ldcg(gi0_t + rowg);

            // ---- matvec via smem ring: 8 chunks; consume slot, then refill it ----
            float acc[8];
#pragma unroll
            for (int i = 0; i < 8; i++) acc[i] = 0.f;
#pragma unroll 1
            for (int c = 0; c < 8; c++) {
                asm volatile("cp.async.wait_group 5;" ::: "memory");
                const uint4* wp = (const uint4*)S->wring + comp_slot * 2048 + warp * 256 + lane;
                const float* hp_s = &S->h_s[c * 64 + warp * 8];
#pragma unroll
                for (int i = 0; i < 8; i++) {
                    uint4 w4 = wp[i * 32];
                    float hk = hp_s[i];
                    const __half2* hp = (const __half2*)&w4;
                    float2 f0 = __half22float2(hp[0]);
                    float2 f1 = __half22float2(hp[1]);
                    float2 f2 = __half22float2(hp[2]);
                    float2 f3 = __half22float2(hp[3]);
                    acc[0] += hk * f0.x; acc[1] += hk * f0.y;
                    acc[2] += hk * f1.x; acc[3] += hk * f1.y;
                    acc[4] += hk * f2.x; acc[5] += hk * f2.y;
                    acc[6] += hk * f3.x; acc[7] += hk * f3.y;
                }
                ISSUE_CHUNK();                   // refill slot just consumed
                if (++comp_slot == RD) comp_slot = 0;
            }
            *(float4*)&S->red[warp][lane * 8]     = make_float4(acc[0], acc[1], acc[2], acc[3]);
            *(float4*)&S->red[warp][lane * 8 + 4] = make_float4(acc[4], acc[5], acc[6], acc[7]);
            __syncthreads();
            float v = gin;
#pragma unroll
            for (int w = 0; w < 8; w++) v += S->red[w][tid];

            // ---- gate LN partial stats (2 warps per gate) ----
            float s = v, q = v * v;
#pragma unroll
            for (int o = 16; o > 0; o >>= 1) {
                s += __shfl_xor_sync(0xffffffffu, s, o);
                q += __shfl_xor_sync(0xffffffffu, q, o);
            }
            if (lane == 0) { S->wpart[warp][0] = s; S->wpart[warp][1] = q; }
            __syncthreads();
            // ---- publish own gate partials: payload store + release tag ----
            if (tid < 4) {
                float2 p;
                p.x = S->wpart[2 * tid][0] + S->wpart[2 * tid + 1][0];
                p.y = S->wpart[2 * tid][1] + S->wpart[2 * tid + 1][1];
                __stcg(&g_stat[(g * 8 + r) * 4 + tid], p);
                st_rel_u32(&g_tag1[(g * 8 + r) * 4 + tid], tag);
            }

            // ---- poll all 8 ranks' tags for my gate, then gather stats ----
            {
                unsigned t0, t1, t2, t3, t4, t5, t6, t7;
                const unsigned* tp = &g_tag1[g * 32 + gate];
                do {
                    t0 = ld_acq_u32(tp +  0); t1 = ld_acq_u32(tp +  4);
                    t2 = ld_acq_u32(tp +  8); t3 = ld_acq_u32(tp + 12);
                    t4 = ld_acq_u32(tp + 16); t5 = ld_acq_u32(tp + 20);
                    t6 = ld_acq_u32(tp + 24); t7 = ld_acq_u32(tp + 28);
                } while (t0 < tag || t1 < tag || t2 < tag || t3 < tag ||
                         t4 < tag || t5 < tag || t6 < tag || t7 < tag);
                float Ssum = 0.f, Q = 0.f;
#pragma unroll
                for (int rr = 0; rr < 8; rr++) {
                    float2 p = __ldcg(&g_stat[g * 32 + rr * 4 + gate]);
                    Ssum += p.x; Q += p.y;
                }
                float mean = Ssum * (1.f / 512.f);
                float var  = Q * (1.f / 512.f) - mean * mean;
                float rstd = rsqrtf(var + EPS);
                float xn = (v - mean) * rstd * S->gwf[(l << 9) + (r << 6) + jl]
                         + S->gbf[(l << 9) + (r << 6) + jl];
                S->act_s[tid] = (gate == 2) ? fast_tanh(xn) : fast_sigmoid(xn);
            }
            __syncthreads();

            // ---- c update + publish (c, o) for own j-slice; release tag after sync ----
            if (tid < 64) {
                c_r = S->act_s[64 + tid] * c_r + S->act_s[tid] * S->act_s[128 + tid];
                __stcg(&g_co[g * 512 + r * 64 + tid], make_float2(c_r, S->act_s[192 + tid]));
            }
            __syncthreads();                       // all (c,o) stores issued
            if (tid == 0) st_rel_u32(&g_tag2[g * 8 + r], tag);

            // ---- poll source ranks for my two j's, then compute global c-stats + h ----
            {
                const unsigned* tq = &g_tag2[g * 8];
                int r0 = tid >> 6, r1 = r0 + 4;    // ranks of j0=tid, j1=tid+256
                unsigned a, b;
                do {
                    a = ld_acq_u32(tq + r0);
                    b = ld_acq_u32(tq + r1);
                } while (a < tag || b < tag);
                float2 p0 = __ldcg(&g_co[g * 512 + tid]);
                float2 p1 = __ldcg(&g_co[g * 512 + 256 + tid]);
                float s2 = p0.x + p1.x, q2 = p0.x * p0.x + p1.x * p1.x;
#pragma unroll
                for (int o = 16; o > 0; o >>= 1) {
                    s2 += __shfl_xor_sync(0xffffffffu, s2, o);
                    q2 += __shfl_xor_sync(0xffffffffu, q2, o);
                }
                if (lane == 0) { S->wpart[warp][0] = s2; S->wpart[warp][1] = q2; }
                __syncthreads();
                float Sc = 0.f, Qc = 0.f;
#pragma unroll
                for (int w = 0; w < 8; w++) { Sc += S->wpart[w][0]; Qc += S->wpart[w][1]; }
                float mean = Sc * (1.f / 512.f);
                float var  = Qc * (1.f / 512.f) - mean * mean;
                float rstd = rsqrtf(var + EPS);
                int j0 = tid, j1 = tid + 256;
                float h0 = p0.y * fast_tanh((p0.x - mean) * rstd * S->gwf[(l << 9) + j0] + S->gbf[(l << 9) + j0]);
                float h1 = p1.y * fast_tanh((p1.x - mean) * rstd * S->gwf[(l << 9) + j1] + S->gbf[(l << 9) + j1]);
                S->h_s[j0] = h0;
                S->h_s[j1] = h1;
                if (l == 1) {
                    float* yt = &y[((size_t)(g * 256 + t)) * 512];
                    if ((j0 >> 6) == r) yt[j0] = h0;
                    if ((j1 >> 6) == r) yt[j1] = h1;
                }
            }
            __syncthreads();
        }
    }
#undef ISSUE_CHUNK
}

// ---------------- launcher ----------------
extern "C" void kernel_launch(void* const* d_in, const int* in_sizes, int n_in,
                              void* d_out, int out_size) {
    (void)in_sizes; (void)n_in; (void)out_size;
    const float* x    = (const float*)d_in[0];
    const float* wih0 = (const float*)d_in[1];
    const float* whh0 = (const float*)d_in[2];
    const float* bih0 = (const float*)d_in[3];
    const float* bhh0 = (const float*)d_in[4];
    const float* wih1 = (const float*)d_in[5];
    const float* whh1 = (const float*)d_in[6];
    const float* bih1 = (const float*)d_in[7];
    const float* bhh1 = (const float*)d_in[8];
    const float* ln_w = (const float*)d_in[9];
    const float* ln_b = (const float*)d_in[10];
    float* y = (float*)d_out;

    cudaFuncSetAttribute(k3_lstm, cudaFuncAttributeMaxDynamicSharedMemorySize,
                         (int)sizeof(K3S));

    k0_init<<<128, 256>>>(bih0, bhh0, bih1, bhh1);
    k1_pack<<<dim3(8, 8, 32), 256>>>(whh0, wih1, whh1);
    k2_gemm<<<dim3(32, 4, 16), 256>>>(wih0, x);
    k3_lstm<<<128, 256, sizeof(K3S)>>>(ln_w, ln_b, y);
}

// round 14
// speedup vs baseline: 1.4660x; 1.4660x over previous
#include <cuda_runtime.h>
#include <cuda_fp16.h>
#include <cstdint>

#define EPS 1e-5f
#define RD 6            // smem ring depth (chunks of 32KB)

// ---------------- device globals (scratch; no allocations allowed) ----------------
// packed recurrent weights: [m][b][r][k=512][rowlocal=256] fp16 ; m=0: whh0, m=1: wih1+whh1
__device__ __half g_warr[2u * 16u * 8u * 512u * 256u];                 // 67.1 MB
__device__ float g_gi0[16u * 256u * 2048u];                            // 33.5 MB: wih0@x + bias0
__device__ float g_bias0[16u * 2048u];
__device__ float g_bias1[16u * 2048u];
__device__ float2 g_stat[16u * 8u * 4u];                               // gate stats: [b][rank][gate]
__device__ float2 g_co[16u * 512u];                                    // (c, o) pairs: [b][j]
__device__ unsigned g_tagA[16u * 8u];                                  // X1 tag per (b, rank)
__device__ unsigned g_tagB[16u * 8u];                                  // X2 tag per (b, rank)

// ---------------- helpers ----------------
__device__ __forceinline__ uint32_t smem_u32(const void* p) {
    uint32_t a;
    asm("{ .reg .u64 t; cvta.to.shared.u64 t, %1; cvt.u32.u64 %0, t; }" : "=r"(a) : "l"(p));
    return a;
}
__device__ __forceinline__ void cpa16(uint32_t dst, const void* src) {
    asm volatile("cp.async.cg.shared.global [%0], [%1], 16;" :: "r"(dst), "l"(src) : "memory");
}
__device__ __forceinline__ void st_rel_u32(unsigned* p, unsigned v) {
    asm volatile("st.release.gpu.global.u32 [%0], %1;" :: "l"(p), "r"(v) : "memory");
}
__device__ __forceinline__ unsigned ld_acq_u32(const unsigned* p) {
    unsigned v;
    asm volatile("ld.acquire.gpu.global.u32 %0, [%1];" : "=r"(v) : "l"(p) : "memory");
    return v;
}
__device__ __forceinline__ float fast_rcp(float x) {
    float r; asm("rcp.approx.f32 %0, %1;" : "=f"(r) : "f"(x)); return r;
}
__device__ __forceinline__ float fast_sigmoid(float x) {
    return fast_rcp(1.0f + __expf(-x));
}
__device__ __forceinline__ float fast_tanh(float x) {
    float r; asm("tanh.approx.f32 %0, %1;" : "=f"(r) : "f"(x)); return r;
}

// distributed-tag group barrier/exchange wait: warp 0 lanes 0..7 poll one rank tag each.
// Callers: producers already released their tag; all CTA threads then call this.
__device__ __forceinline__ void wait_tags(const unsigned* tags8, unsigned tag,
                                          int warp, int lane) {
    if (warp == 0) {
        if (lane < 8) {
            while (ld_acq_u32(tags8 + lane) < tag) { }
        }
        __syncwarp();
    }
    __syncthreads();
}

// ---------------- K0: per-launch init ----------------
__global__ void k0_init(const float* __restrict__ bih0, const float* __restrict__ bhh0,
                        const float* __restrict__ bih1, const float* __restrict__ bhh1) {
    int i = blockIdx.x * blockDim.x + threadIdx.x;   // 32768 = 16*2048
    g_bias0[i] = bih0[i] + bhh0[i];
    g_bias1[i] = bih1[i] + bhh1[i];
    if (i < 128) { g_tagA[i] = 0u; g_tagB[i] = 0u; }
}

// ---------------- K1: pack/transpose recurrent weights to fp16 [k][row] ----------------
// grid (8 ktile, 8 rank, 32 = m*16+b), 256 threads; tile = 64 k x 256 rows
__global__ void k1_pack(const float* __restrict__ whh0, const float* __restrict__ wih1,
                        const float* __restrict__ whh1) {
    __shared__ __align__(16) __half sm[64 * 264];
    int kt = blockIdx.x, r = blockIdx.y;
    int mb = blockIdx.z; int m = mb >> 4, b = mb & 15;
    int tid = threadIdx.x;
    int grow = ((tid >> 6) << 9) + (r << 6) + (tid & 63);
    int k0 = kt * 64;
    const float* s0 = (m == 0 ? whh0 : wih1) + ((size_t)(b * 2048 + grow) * 512 + k0);
    const float* s1 = whh1 + ((size_t)(b * 2048 + grow) * 512 + k0);
#pragma unroll
    for (int q = 0; q < 16; q++) {
        float4 v = *(const float4*)(s0 + q * 4);
        if (m) {
            float4 u = *(const float4*)(s1 + q * 4);
            v.x += u.x; v.y += u.y; v.z += u.z; v.w += u.w;
        }
        sm[(q * 4 + 0) * 264 + tid] = __float2half(v.x);
        sm[(q * 4 + 1) * 264 + tid] = __float2half(v.y);
        sm[(q * 4 + 2) * 264 + tid] = __float2half(v.z);
        sm[(q * 4 + 3) * 264 + tid] = __float2half(v.w);
    }
    __syncthreads();
    __half* out = &g_warr[(((size_t)mb) * 8u + r) * 512u * 256u + (size_t)k0 * 256u];
    int kk = tid >> 2, rb = (tid & 3) * 64;
    const uint4* src = (const uint4*)(sm + kk * 264 + rb);
    uint4* dst = (uint4*)(out + kk * 256 + rb);
#pragma unroll
    for (int q = 0; q < 8; q++) dst[q] = src[q];
}

// ---------------- K2: precompute gi0[b][t][row] = wih0@x_t + bias0 ----------------
__global__ void k2_gemm(const float* __restrict__ wih0, const float* __restrict__ x) {
    __shared__ float As[64][17];
    __shared__ float Bs[16][65];
    int rt = blockIdx.x, tt = blockIdx.y, b = blockIdx.z;
    int row0 = rt * 64, t0 = tt * 64;
    int tid = threadIdx.x;
    int lm = tid >> 2, kq = tid & 3;
    const float* Ap = wih0 + ((size_t)(b * 2048 + row0 + lm) * 512 + kq * 4);
    const float* Bp = x + ((size_t)(b * 256 + t0 + lm) * 512 + kq * 4);
    int ty = tid >> 4, tx = tid & 15;
    float C[4][4];
#pragma unroll
    for (int i = 0; i < 4; i++)
#pragma unroll
        for (int j = 0; j < 4; j++) C[i][j] = 0.f;

    for (int kc = 0; kc < 512; kc += 16) {
        float4 a4 = *(const float4*)(Ap + kc);
        float4 b4 = *(const float4*)(Bp + kc);
        As[lm][kq * 4 + 0] = a4.x; As[lm][kq * 4 + 1] = a4.y;
        As[lm][kq * 4 + 2] = a4.z; As[lm][kq * 4 + 3] = a4.w;
        Bs[kq * 4 + 0][lm] = b4.x; Bs[kq * 4 + 1][lm] = b4.y;
        Bs[kq * 4 + 2][lm] = b4.z; Bs[kq * 4 + 3][lm] = b4.w;
        __syncthreads();
#pragma unroll
        for (int kk = 0; kk < 16; kk++) {
            float a[4], bb[4];
#pragma unroll
            for (int i = 0; i < 4; i++) a[i] = As[ty * 4 + i][kk];
#pragma unroll
            for (int j = 0; j < 4; j++) bb[j] = Bs[kk][tx * 4 + j];
#pragma unroll
            for (int i = 0; i < 4; i++)
#pragma unroll
                for (int j = 0; j < 4; j++) C[i][j] += a[i] * bb[j];
        }
        __syncthreads();
    }
    float4 bias = *(const float4*)&g_bias0[b * 2048 + row0 + ty * 4];
#pragma unroll
    for (int j = 0; j < 4; j++) {
        float4 vo;
        vo.x = C[0][j] + bias.x; vo.y = C[1][j] + bias.y;
        vo.z = C[2][j] + bias.z; vo.w = C[3][j] + bias.w;
        *(float4*)&g_gi0[((size_t)(b * 256 + t0 + tx * 4 + j)) * 2048 + row0 + ty * 4] = vo;
    }
}

// ---------------- K3: persistent recurrent kernel ----------------
// 128 CTAs x 256 threads. group g = batch, rank r owns h[64r..64r+64) + its 256 gate rows.
// Weight stream via 6-slot cp.async ring. Cross-CTA sync: per-rank monotonic release-tags,
// polled by warp 0 only (8 lanes, 1 tag each) -> 8 poll loads/round/CTA, no central atomic.
struct K3S {
    __half wring[RD * 64 * 256];   // 196608 B: RD chunk slots, [k64][row256]
    float h_s[512];
    float red[8][256];
    float act_s[256];
    float wpart[8][2];
    float gwf[1024], gbf[1024];    // LN params, both layers
    float bias1_s[256];
};

__global__ void __launch_bounds__(256, 1)
k3_lstm(const float* __restrict__ ln_w, const float* __restrict__ ln_b, float* __restrict__ y) {
    extern __shared__ __align__(16) unsigned char sraw[];
    K3S* S = (K3S*)sraw;

    int bid = blockIdx.x;
    int g = bid >> 3, r = bid & 7;
    int tid = threadIdx.x, warp = tid >> 5, lane = tid & 31;
    int gate = tid >> 6, jl = tid & 63;

    const uint4* Wl[2];
    Wl[0] = (const uint4*)&g_warr[(((size_t)(0 * 16 + g)) * 8u + r) * 512u * 256u];
    Wl[1] = (const uint4*)&g_warr[(((size_t)(1 * 16 + g)) * 8u + r) * 512u * 256u];
    uint32_t wring_a = smem_u32(S->wring) + (uint32_t)(warp * 256 + lane) * 16u;

    int iss_it = 0, iss_c = 0, iss_slot = 0;
#define ISSUE_CHUNK() do {                                                          \
        if (iss_it < 512) {                                                         \
            const uint4* _src = Wl[iss_it & 1] + (size_t)((iss_c * 64 + warp * 8) * 32 + lane); \
            uint32_t _dst = wring_a + (uint32_t)(iss_slot * 32768);                 \
            _Pragma("unroll")                                                       \
            for (int _i = 0; _i < 8; _i++) cpa16(_dst + _i * 512u, _src + _i * 32); \
        }                                                                           \
        asm volatile("cp.async.commit_group;" ::: "memory");                        \
        if (++iss_c == 8) { iss_c = 0; iss_it++; }                                  \
        if (++iss_slot == RD) iss_slot = 0;                                         \
    } while (0)

    // prologue: fill the whole ring (6 chunks ahead), init state
    ISSUE_CHUNK(); ISSUE_CHUNK(); ISSUE_CHUNK();
    ISSUE_CHUNK(); ISSUE_CHUNK(); ISSUE_CHUNK();
    S->h_s[tid] = 0.f; S->h_s[tid + 256] = 0.f;
    for (int i = tid; i < 1024; i += 256) { S->gwf[i] = ln_w[i]; S->gbf[i] = ln_b[i]; }
    S->bias1_s[tid] = g_bias1[g * 2048 + (gate << 9) + (r << 6) + jl];
    __syncthreads();

    float c_r = 0.f;           // cell state: thread tid<64 owns j = r*64 + tid
    unsigned tag = 0;
    int comp_slot = 0;

    for (int t = 0; t < 256; t++) {
        const float* gi0_t = &g_gi0[((size_t)(g * 256 + t)) * 2048];
        for (int l = 0; l < 2; l++) {
            tag++;

            // ---- per-row additive term (issue load early) ----
            int rowg = (gate << 9) + (r << 6) + jl;
            float gin = l ? S->bias1_s[tid] : __ldcg(gi0_t + rowg);

            // ---- matvec via smem ring: 8 chunks; consume slot, then refill it ----
            float acc[8];
#pragma unroll
            for (int i = 0; i < 8; i++) acc[i] = 0.f;
#pragma unroll 1
            for (int c = 0; c < 8; c++) {
                asm volatile("cp.async.wait_group 5;" ::: "memory");
                const uint4* wp = (const uint4*)S->wring + comp_slot * 2048 + warp * 256 + lane;
                const float* hp_s = &S->h_s[c * 64 + warp * 8];
#pragma unroll
                for (int i = 0; i < 8; i++) {
                    uint4 w4 = wp[i * 32];
                    float hk = hp_s[i];
                    const __half2* hp = (const __half2*)&w4;
                    float2 f0 = __half22float2(hp[0]);
                    float2 f1 = __half22float2(hp[1]);
                    float2 f2 = __half22float2(hp[2]);
                    float2 f3 = __half22float2(hp[3]);
                    acc[0] += hk * f0.x; acc[1] += hk * f0.y;
                    acc[2] += hk * f1.x; acc[3] += hk * f1.y;
                    acc[4] += hk * f2.x; acc[5] += hk * f2.y;
                    acc[6] += hk * f3.x; acc[7] += hk * f3.y;
                }
                ISSUE_CHUNK();                   // refill slot just consumed
                if (++comp_slot == RD) comp_slot = 0;
            }
            *(float4*)&S->red[warp][lane * 8]     = make_float4(acc[0], acc[1], acc[2], acc[3]);
            *(float4*)&S->red[warp][lane * 8 + 4] = make_float4(acc[4], acc[5], acc[6], acc[7]);
            __syncthreads();
            float v = gin;
#pragma unroll
            for (int w = 0; w < 8; w++) v += S->red[w][tid];

            // ---- gate LN partial stats (2 warps per gate) ----
            float s = v, q = v * v;
#pragma unroll
            for (int o = 16; o > 0; o >>= 1) {
                s += __shfl_xor_sync(0xffffffffu, s, o);
                q += __shfl_xor_sync(0xffffffffu, q, o);
            }
            if (lane == 0) { S->wpart[warp][0] = s; S->wpart[warp][1] = q; }
            __syncthreads();
            // ---- X1 publish: payload stores (warp 0 lanes 0..3) + lane-0 release tag ----
            if (warp == 0) {
                if (lane < 4) {
                    float2 p;
                    p.x = S->wpart[2 * lane][0] + S->wpart[2 * lane + 1][0];
                    p.y = S->wpart[2 * lane][1] + S->wpart[2 * lane + 1][1];
                    __stcg(&g_stat[(g * 8 + r) * 4 + lane], p);
                }
                __syncwarp();
                if (lane == 0) st_rel_u32(&g_tagA[g * 8 + r], tag);
            }
            wait_tags(&g_tagA[g * 8], tag, warp, lane);    // X1: all ranks' stats visible

            // ---- finalize gate LN + activation ----
            {
                float Ssum = 0.f, Q = 0.f;
#pragma unroll
                for (int rr = 0; rr < 8; rr++) {
                    float2 p = __ldcg(&g_stat[g * 32 + rr * 4 + gate]);
                    Ssum += p.x; Q += p.y;
                }
                float mean = Ssum * (1.f / 512.f);
                float var  = Q * (1.f / 512.f) - mean * mean;
                float rstd = rsqrtf(var + EPS);
                float xn = (v - mean) * rstd * S->gwf[(l << 9) + (r << 6) + jl]
                         + S->gbf[(l << 9) + (r << 6) + jl];
                S->act_s[tid] = (gate == 2) ? fast_tanh(xn) : fast_sigmoid(xn);
            }
            __syncthreads();

            // ---- c update + X2 publish (c, o) for own j-slice ----
            if (tid < 64) {
                c_r = S->act_s[64 + tid] * c_r + S->act_s[tid] * S->act_s[128 + tid];
                __stcg(&g_co[g * 512 + r * 64 + tid], make_float2(c_r, S->act_s[192 + tid]));
            }
            __syncthreads();                       // all (c,o) stores issued
            if (tid == 0) st_rel_u32(&g_tagB[g * 8 + r], tag);
            wait_tags(&g_tagB[g * 8], tag, warp, lane);    // X2: all (c,o) pairs visible

            // ---- merged: every rank computes global c-stats + full h locally ----
            float2 p0 = __ldcg(&g_co[g * 512 + tid]);         // j = tid
            float2 p1 = __ldcg(&g_co[g * 512 + 256 + tid]);   // j = tid + 256
            {
                float s2 = p0.x + p1.x, q2 = p0.x * p0.x + p1.x * p1.x;
#pragma unroll
                for (int o = 16; o > 0; o >>= 1) {
                    s2 += __shfl_xor_sync(0xffffffffu, s2, o);
                    q2 += __shfl_xor_sync(0xffffffffu, q2, o);
                }
                if (lane == 0) { S->wpart[warp][0] = s2; S->wpart[warp][1] = q2; }
            }
            __syncthreads();
            {
                float Sc = 0.f, Qc = 0.f;
#pragma unroll
                for (int w = 0; w < 8; w++) { Sc += S->wpart[w][0]; Qc += S->wpart[w][1]; }
                float mean = Sc * (1.f / 512.f);
                float var  = Qc * (1.f / 512.f) - mean * mean;
                float rstd = rsqrtf(var + EPS);
                int j0 = tid, j1 = tid + 256;
                float h0 = p0.y * fast_tanh((p0.x - mean) * rstd * S->gwf[(l << 9) + j0] + S->gbf[(l << 9) + j0]);
                float h1 = p1.y * fast_tanh((p1.x - mean) * rstd * S->gwf[(l << 9) + j1] + S->gbf[(l << 9) + j1]);
                S->h_s[j0] = h0;
                S->h_s[j1] = h1;
                if (l == 1) {
                    float* yt = &y[((size_t)(g * 256 + t)) * 512];
                    if ((j0 >> 6) == r) yt[j0] = h0;
                    if ((j1 >> 6) == r) yt[j1] = h1;
                }
            }
            __syncthreads();
        }
    }
#undef ISSUE_CHUNK
}

// ---------------- launcher ----------------
extern "C" void kernel_launch(void* const* d_in, const int* in_sizes, int n_in,
                              void* d_out, int out_size) {
    (void)in_sizes; (void)n_in; (void)out_size;
    const float* x    = (const float*)d_in[0];
    const float* wih0 = (const float*)d_in[1];
    const float* whh0 = (const float*)d_in[2];
    const float* bih0 = (const float*)d_in[3];
    const float* bhh0 = (const float*)d_in[4];
    const float* wih1 = (const float*)d_in[5];
    const float* whh1 = (const float*)d_in[6];
    const float* bih1 = (const float*)d_in[7];
    const float* bhh1 = (const float*)d_in[8];
    const float* ln_w = (const float*)d_in[9];
    const float* ln_b = (const float*)d_in[10];
    float* y = (float*)d_out;

    cudaFuncSetAttribute(k3_lstm, cudaFuncAttributeMaxDynamicSharedMemorySize,
                         (int)sizeof(K3S));

    k0_init<<<128, 256>>>(bih0, bhh0, bih1, bhh1);
    k1_pack<<<dim3(8, 8, 32), 256>>>(whh0, wih1, whh1);
    k2_gemm<<<dim3(32, 4, 16), 256>>>(wih0, x);
    k3_lstm<<<128, 256, sizeof(K3S)>>>(ln_w, ln_b, y);
}

// round 15
// speedup vs baseline: 1.5175x; 1.0351x over previous
#include <cuda_runtime.h>
#include <cuda_fp16.h>
#include <cstdint>

#define EPS 1e-5f
#define RD 11           // smem ring depth (chunks of 16KB)

// ---------------- device globals (scratch; no allocations allowed) ----------------
// packed recurrent weights: [m][b][R16][k=512][rowlocal=128] fp16 ; m=0: whh0, m=1: wih1+whh1
__device__ __half g_warr[2u * 16u * 16u * 512u * 128u];                // 67.1 MB
__device__ float g_gi0[16u * 256u * 2048u];                            // 33.5 MB: wih0@x + bias0
__device__ float g_bias0[16u * 2048u];
__device__ float g_bias1[16u * 2048u];
__device__ float2 g_stat[16u * 16u * 4u];                              // gate stats: [b][R][gate]
__device__ float2 g_co[16u * 512u];                                    // (c, o) pairs: [b][j]
__device__ unsigned g_cnt[8u * 4u];                                    // [pair][stream]
__device__ unsigned g_flag[8u * 4u];

// ---------------- helpers ----------------
__device__ __forceinline__ uint32_t smem_u32(const void* p) {
    uint32_t a;
    asm("{ .reg .u64 t; cvta.to.shared.u64 t, %1; cvt.u32.u64 %0, t; }" : "=r"(a) : "l"(p));
    return a;
}
__device__ __forceinline__ void cpa16(uint32_t dst, const void* src) {
    asm volatile("cp.async.cg.shared.global [%0], [%1], 16;" :: "r"(dst), "l"(src) : "memory");
}
__device__ __forceinline__ float fast_rcp(float x) {
    float r; asm("rcp.approx.f32 %0, %1;" : "=f"(r) : "f"(x)); return r;
}
__device__ __forceinline__ float fast_sigmoid(float x) {
    return fast_rcp(1.0f + __expf(-x));
}
__device__ __forceinline__ float fast_tanh(float x) {
    return 2.0f * fast_rcp(1.0f + __expf(-2.0f * x)) - 1.0f;
}
// arrive/wait split barrier (R10 mechanism: central counter + single flag word)
__device__ __forceinline__ void bar_arrive(int slot, unsigned tag) {
    unsigned v;
    asm volatile("atom.add.acq_rel.gpu.global.u32 %0, [%1], 1;"
                 : "=r"(v) : "l"(&g_cnt[slot]) : "memory");
    if (v + 1u == tag * 16u) {
        asm volatile("st.release.gpu.global.u32 [%0], %1;"
                     :: "l"(&g_flag[slot]), "r"(tag) : "memory");
    }
}
__device__ __forceinline__ void bar_poll(int slot, unsigned tag) {
    unsigned f;
    do {
        asm volatile("ld.acquire.gpu.global.u32 %0, [%1];"
                     : "=r"(f) : "l"(&g_flag[slot]) : "memory");
    } while (f < tag);
}

// ---------------- K0: per-launch init ----------------
__global__ void k0_init(const float* __restrict__ bih0, const float* __restrict__ bhh0,
                        const float* __restrict__ bih1, const float* __restrict__ bhh1) {
    int i = blockIdx.x * blockDim.x + threadIdx.x;   // 32768 = 16*2048
    g_bias0[i] = bih0[i] + bhh0[i];
    g_bias1[i] = bih1[i] + bhh1[i];
    if (i < 32) { g_cnt[i] = 0u; g_flag[i] = 0u; }
}

// ---------------- K1: pack/transpose recurrent weights to fp16 [k][row128] ----------------
// grid (8 ktile, 16 R, 32 = m*16+b), 256 threads; tile = 64 k x 128 rows
#define K1PAD 136
__global__ void k1_pack(const float* __restrict__ whh0, const float* __restrict__ wih1,
                        const float* __restrict__ whh1) {
    __shared__ __align__(16) __half sm[64 * K1PAD];
    int kt = blockIdx.x, R = blockIdx.y;
    int mb = blockIdx.z; int m = mb >> 4, b = mb & 15;
    int tid = threadIdx.x;
    int rowlocal = tid >> 1, khalf = tid & 1;
    int grow = ((rowlocal >> 5) << 9) + (R << 5) + (rowlocal & 31);  // gate*512 + R*32 + j
    int k0 = kt * 64 + khalf * 32;
    const float* s0 = (m == 0 ? whh0 : wih1) + ((size_t)(b * 2048 + grow) * 512 + k0);
    const float* s1 = whh1 + ((size_t)(b * 2048 + grow) * 512 + k0);
#pragma unroll
    for (int q = 0; q < 8; q++) {
        float4 v = *(const float4*)(s0 + q * 4);
        if (m) {
            float4 u = *(const float4*)(s1 + q * 4);
            v.x += u.x; v.y += u.y; v.z += u.z; v.w += u.w;
        }
        int kk = khalf * 32 + q * 4;
        sm[(kk + 0) * K1PAD + rowlocal] = __float2half(v.x);
        sm[(kk + 1) * K1PAD + rowlocal] = __float2half(v.y);
        sm[(kk + 2) * K1PAD + rowlocal] = __float2half(v.z);
        sm[(kk + 3) * K1PAD + rowlocal] = __float2half(v.w);
    }
    __syncthreads();
    __half* out = g_warr + (((size_t)(m * 16 + b) * 16 + R) * 512 + (size_t)kt * 64) * 128;
    int kk = tid >> 2, pp = tid & 3;
    const uint4* src = (const uint4*)(sm + kk * K1PAD + pp * 32);
    uint4* dst = (uint4*)(out + kk * 128 + pp * 32);
#pragma unroll
    for (int q = 0; q < 4; q++) dst[q] = src[q];
}

// ---------------- K2: precompute gi0[b][t][row] = wih0@x_t + bias0 ----------------
__global__ void k2_gemm(const float* __restrict__ wih0, const float* __restrict__ x) {
    __shared__ float As[64][17];
    __shared__ float Bs[16][65];
    int rt = blockIdx.x, tt = blockIdx.y, b = blockIdx.z;
    int row0 = rt * 64, t0 = tt * 64;
    int tid = threadIdx.x;
    int lm = tid >> 2, kq = tid & 3;
    const float* Ap = wih0 + ((size_t)(b * 2048 + row0 + lm) * 512 + kq * 4);
    const float* Bp = x + ((size_t)(b * 256 + t0 + lm) * 512 + kq * 4);
    int ty = tid >> 4, tx = tid & 15;
    float C[4][4];
#pragma unroll
    for (int i = 0; i < 4; i++)
#pragma unroll
        for (int j = 0; j < 4; j++) C[i][j] = 0.f;

    for (int kc = 0; kc < 512; kc += 16) {
        float4 a4 = *(const float4*)(Ap + kc);
        float4 b4 = *(const float4*)(Bp + kc);
        As[lm][kq * 4 + 0] = a4.x; As[lm][kq * 4 + 1] = a4.y;
        As[lm][kq * 4 + 2] = a4.z; As[lm][kq * 4 + 3] = a4.w;
        Bs[kq * 4 + 0][lm] = b4.x; Bs[kq * 4 + 1][lm] = b4.y;
        Bs[kq * 4 + 2][lm] = b4.z; Bs[kq * 4 + 3][lm] = b4.w;
        __syncthreads();
#pragma unroll
        for (int kk = 0; kk < 16; kk++) {
            float a[4], bb[4];
#pragma unroll
            for (int i = 0; i < 4; i++) a[i] = As[ty * 4 + i][kk];
#pragma unroll
            for (int j = 0; j < 4; j++) bb[j] = Bs[kk][tx * 4 + j];
#pragma unroll
            for (int i = 0; i < 4; i++)
#pragma unroll
                for (int j = 0; j < 4; j++) C[i][j] += a[i] * bb[j];
        }
        __syncthreads();
    }
    float4 bias = *(const float4*)&g_bias0[b * 2048 + row0 + ty * 4];
#pragma unroll
    for (int j = 0; j < 4; j++) {
        float4 vo;
        vo.x = C[0][j] + bias.x; vo.y = C[1][j] + bias.y;
        vo.z = C[2][j] + bias.z; vo.w = C[3][j] + bias.w;
        *(float4*)&g_gi0[((size_t)(b * 256 + t0 + tx * 4 + j)) * 2048 + row0 + ty * 4] = vo;
    }
}

// ---------------- K3: persistent recurrent kernel, batch-pair pipelined ----------------
// 128 CTAs = 8 pair-groups x 16 ranks, 256 threads. Rank R owns j [32R,32R+32) and
// 128 gate rows per batch, for BOTH batches of its pair. Cross-CTA waits are hidden
// behind the other batch's matvec/LN work. Sync: arrive-early/wait-late cnt+flag barriers.
struct K3S {
    __half wring[RD * 64 * 128];   // RD x 16KB chunk slots, [k64][row128]
    float h_s[2][512];
    float red[16][128];
    float act_s[2][128];
    float wpart[8][2];
    float gwf[1024], gbf[1024];    // LN params, both layers
    float bias1_s[2][128];
};

__global__ void __launch_bounds__(256, 1)
k3_lstm(const float* __restrict__ ln_w, const float* __restrict__ ln_b, float* __restrict__ y) {
    extern __shared__ __align__(16) unsigned char sraw[];
    K3S* S = (K3S*)sraw;

    int bid = blockIdx.x;
    int pair = bid >> 4, R = bid & 15;
    int bA = pair * 2, bB = bA + 1;
    int tid = threadIdx.x, warp = tid >> 5, lane = tid & 31;
    int khalf = lane >> 4, rowg = lane & 15;
    int slotX1A = pair * 4 + 0, slotX1B = pair * 4 + 1;
    int slotX2A = pair * 4 + 2, slotX2B = pair * 4 + 3;

    const uint4* Wb[2][2];
#pragma unroll
    for (int m = 0; m < 2; m++)
#pragma unroll
        for (int hf = 0; hf < 2; hf++)
            Wb[m][hf] = (const uint4*)g_warr + ((size_t)(m * 16 + bA + hf) * 16 + R) * 512 * 16;

    uint32_t ring0 = smem_u32(S->wring);
    int iss_iter = 0, iss_half = 0, iss_c = 0, iss_slot = 0;
#define ISSUE_CHUNK() do {                                                              \
        if (iss_iter < 512) {                                                           \
            const uint4* _b = Wb[iss_iter & 1][iss_half];                               \
            int _kin = lane >> 2, _q = lane & 3;                                        \
            const uint4* _src = _b + (size_t)(iss_c * 64 + warp * 8 + _kin) * 16 + _q * 4; \
            uint32_t _dst = ring0 + (uint32_t)(iss_slot * 16384 +                       \
                                ((warp * 8 + _kin) * 16 + _q * 4) * 16);                \
            cpa16(_dst,      _src);     cpa16(_dst + 16, _src + 1);                     \
            cpa16(_dst + 32, _src + 2); cpa16(_dst + 48, _src + 3);                     \
        }                                                                               \
        asm volatile("cp.async.commit_group;" ::: "memory");                            \
        if (++iss_c == 8) { iss_c = 0; if (++iss_half == 2) { iss_half = 0; ++iss_iter; } } \
        if (++iss_slot == RD) iss_slot = 0;                                             \
    } while (0)

    // prologue: fill ring, init state
#pragma unroll
    for (int p = 0; p < RD; p++) ISSUE_CHUNK();
    S->h_s[0][tid] = 0.f; S->h_s[0][tid + 256] = 0.f;
    S->h_s[1][tid] = 0.f; S->h_s[1][tid + 256] = 0.f;
    for (int i = tid; i < 1024; i += 256) { S->gwf[i] = ln_w[i]; S->gbf[i] = ln_b[i]; }
    if (tid < 128) {
        int rowg2 = (tid >> 5) * 512 + (R << 5) + (tid & 31);
        S->bias1_s[0][tid] = g_bias1[bA * 2048 + rowg2];
        S->bias1_s[1][tid] = g_bias1[bB * 2048 + rowg2];
    }
    __syncthreads();

    float cA = 0.f, cB = 0.f;     // cell state: tid<32 owns j = R*32 + tid
    unsigned tag = 0;
    int comp_slot = 0;

    for (int t = 0; t < 256; t++) {
        for (int l = 0; l < 2; l++) {
            tag++;
            float ginA = 0.f, ginB = 0.f, vA = 0.f, vB = 0.f;
            if (tid < 128) {
                int rowg2 = (tid >> 5) * 512 + (R << 5) + (tid & 31);
                if (l) { ginA = S->bias1_s[0][tid]; ginB = S->bias1_s[1][tid]; }
                else {
                    ginA = __ldcg(&g_gi0[((size_t)(bA * 256 + t)) * 2048 + rowg2]);
                    ginB = __ldcg(&g_gi0[((size_t)(bB * 256 + t)) * 2048 + rowg2]);
                }
            }

            // ================= matvec + publish, batches A then B =================
#pragma unroll 1
            for (int hf = 0; hf < 2; hf++) {
                float acc[8];
#pragma unroll
                for (int i = 0; i < 8; i++) acc[i] = 0.f;
#pragma unroll 1
                for (int c = 0; c < 8; c++) {
                    asm volatile("cp.async.wait_group %0;" :: "n"(RD - 1));
                    const uint4* wp = (const uint4*)S->wring + comp_slot * 1024
                                    + (warp * 8 + khalf) * 16 + rowg;
                    const float* hb = &S->h_s[hf][c * 64 + warp * 8 + khalf];
#pragma unroll
                    for (int i = 0; i < 4; i++) {
                        uint4 w4 = wp[32 * i];
                        float hk = hb[2 * i];
                        const __half2* hp = (const __half2*)&w4;
                        float2 f0 = __half22float2(hp[0]);
                        float2 f1 = __half22float2(hp[1]);
                        float2 f2 = __half22float2(hp[2]);
                        float2 f3 = __half22float2(hp[3]);
                        acc[0] += hk * f0.x; acc[1] += hk * f0.y;
                        acc[2] += hk * f1.x; acc[3] += hk * f1.y;
                        acc[4] += hk * f2.x; acc[5] += hk * f2.y;
                        acc[6] += hk * f3.x; acc[7] += hk * f3.y;
                    }
                    ISSUE_CHUNK();
                    if (++comp_slot == RD) comp_slot = 0;
                }
                *(float4*)&S->red[warp * 2 + khalf][rowg * 8]     = make_float4(acc[0], acc[1], acc[2], acc[3]);
                *(float4*)&S->red[warp * 2 + khalf][rowg * 8 + 4] = make_float4(acc[4], acc[5], acc[6], acc[7]);
                __syncthreads();
                float v = hf ? ginB : ginA;
                if (tid < 128) {
#pragma unroll
                    for (int s = 0; s < 16; s++) v += S->red[s][tid];
                    float sP = v, qP = v * v;
#pragma unroll
                    for (int o = 16; o > 0; o >>= 1) {
                        sP += __shfl_xor_sync(0xffffffffu, sP, o);
                        qP += __shfl_xor_sync(0xffffffffu, qP, o);
                    }
                    if (lane == 0)
                        __stcg(&g_stat[((hf ? bB : bA) * 16 + R) * 4 + warp], make_float2(sP, qP));
                }
                if (hf) vB = v; else vA = v;
                __syncthreads();      // red free + stat stores done before arrive
                if (tid == 0) bar_arrive(hf ? slotX1B : slotX1A, tag);
            }

            // ================= LN + activation + c-update, A then B =================
#pragma unroll 1
            for (int hf = 0; hf < 2; hf++) {
                if (tid == 0) bar_poll(hf ? slotX1B : slotX1A, tag);
                __syncthreads();
                int b = hf ? bB : bA;
                if (tid < 128) {
                    float v = hf ? vB : vA;
                    int gate = tid >> 5, jl = tid & 31;
                    float Ssum = 0.f, Q = 0.f;
#pragma unroll
                    for (int rr = 0; rr < 16; rr++) {
                        float2 p = __ldcg(&g_stat[(b * 16 + rr) * 4 + gate]);
                        Ssum += p.x; Q += p.y;
                    }
                    float mean = Ssum * (1.f / 512.f);
                    float var  = Q * (1.f / 512.f) - mean * mean;
                    float rstd = rsqrtf(var + EPS);
                    int gidx = (l << 9) + (R << 5) + jl;
                    float xn = (v - mean) * rstd * S->gwf[gidx] + S->gbf[gidx];
                    S->act_s[hf][tid] = (gate == 2) ? fast_tanh(xn) : fast_sigmoid(xn);
                }
                __syncthreads();
                if (tid < 32) {
                    float cv = hf ? cB : cA;
                    cv = S->act_s[hf][32 + tid] * cv + S->act_s[hf][tid] * S->act_s[hf][64 + tid];
                    if (hf) cB = cv; else cA = cv;
                    __stcg(&g_co[b * 512 + (R << 5) + tid], make_float2(cv, S->act_s[hf][96 + tid]));
                }
                __syncthreads();
                if (tid == 0) bar_arrive(hf ? slotX2B : slotX2A, tag);
            }

            // ================= global c-stats + full h, A then B =================
#pragma unroll 1
            for (int hf = 0; hf < 2; hf++) {
                if (tid == 0) bar_poll(hf ? slotX2B : slotX2A, tag);
                __syncthreads();
                int b = hf ? bB : bA;
                float2 p0 = __ldcg(&g_co[b * 512 + tid]);
                float2 p1 = __ldcg(&g_co[b * 512 + 256 + tid]);
                float s2 = p0.x + p1.x, q2 = p0.x * p0.x + p1.x * p1.x;
#pragma unroll
                for (int o = 16; o > 0; o >>= 1) {
                    s2 += __shfl_xor_sync(0xffffffffu, s2, o);
                    q2 += __shfl_xor_sync(0xffffffffu, q2, o);
                }
                if (lane == 0) { S->wpart[warp][0] = s2; S->wpart[warp][1] = q2; }
                __syncthreads();
                float Sc = 0.f, Qc = 0.f;
#pragma unroll
                for (int w = 0; w < 8; w++) { Sc += S->wpart[w][0]; Qc += S->wpart[w][1]; }
                float mean = Sc * (1.f / 512.f);
                float var  = Qc * (1.f / 512.f) - mean * mean;
                float rstd = rsqrtf(var + EPS);
                int j0 = tid, j1 = tid + 256;
                float h0 = p0.y * fast_tanh((p0.x - mean) * rstd * S->gwf[(l << 9) + j0] + S->gbf[(l << 9) + j0]);
                float h1 = p1.y * fast_tanh((p1.x - mean) * rstd * S->gwf[(l << 9) + j1] + S->gbf[(l << 9) + j1]);
                S->h_s[hf][j0] = h0;
                S->h_s[hf][j1] = h1;
                if (l == 1) {
                    float* yt = &y[((size_t)(b * 256 + t)) * 512];
                    if ((j0 >> 5) == R) yt[j0] = h0;
                    if ((j1 >> 5) == R) yt[j1] = h1;
                }
            }
            __syncthreads();
        }
    }
#undef ISSUE_CHUNK
}

// ---------------- launcher ----------------
extern "C" void kernel_launch(void* const* d_in, const int* in_sizes, int n_in,
                              void* d_out, int out_size) {
    (void)in_sizes; (void)n_in; (void)out_size;
    const float* x    = (const float*)d_in[0];
    const float* wih0 = (const float*)d_in[1];
    const float* whh0 = (const float*)d_in[2];
    const float* bih0 = (const float*)d_in[3];
    const float* bhh0 = (const float*)d_in[4];
    const float* wih1 = (const float*)d_in[5];
    const float* whh1 = (const float*)d_in[6];
    const float* bih1 = (const float*)d_in[7];
    const float* bhh1 = (const float*)d_in[8];
    const float* ln_w = (const float*)d_in[9];
    const float* ln_b = (const float*)d_in[10];
    float* y = (float*)d_out;

    cudaFuncSetAttribute(k3_lstm, cudaFuncAttributeMaxDynamicSharedMemorySize,
                         (int)sizeof(K3S));

    k0_init<<<128, 256>>>(bih0, bhh0, bih1, bhh1);
    k1_pack<<<dim3(8, 16, 32), 256>>>(whh0, wih1, whh1);
    k2_gemm<<<dim3(32, 4, 16), 256>>>(wih0, x);
    k3_lstm<<<128, 256, sizeof(K3S)>>>(ln_w, ln_b, y);
}

// round 16
// speedup vs baseline: 2.4159x; 1.5920x over previous
#include <cuda_runtime.h>
#include <cuda_fp16.h>
#include <cstdint>

#define EPS 1e-5f
#define RD 6            // smem ring depth (chunks of 32KB)

// ---------------- device globals (scratch; no allocations allowed) ----------------
// packed recurrent weights: [m][b][r][k=512][rowlocal=256] fp16 ; m=0: whh0, m=1: wih1+whh1
__device__ __half g_warr[2u * 16u * 8u * 512u * 256u];                 // 67.1 MB
__device__ float g_gi0[16u * 256u * 2048u];                            // 33.5 MB: wih0@x + bias0
__device__ float g_bias0[16u * 2048u];
__device__ float g_bias1[16u * 2048u];
__device__ float2 g_stat[16u * 8u * 4u];                               // gate stats: [b][rank][gate]
__device__ float2 g_co[16u * 512u];                                    // (c, o) pairs: [b][j]
__device__ unsigned g_cnt[32];                                         // [group][phase]
__device__ unsigned g_flag[32];

// ---------------- helpers ----------------
__device__ __forceinline__ uint32_t smem_u32(const void* p) {
    uint32_t a;
    asm("{ .reg .u64 t; cvta.to.shared.u64 t, %1; cvt.u32.u64 %0, t; }" : "=r"(a) : "l"(p));
    return a;
}
__device__ __forceinline__ void cpa16(uint32_t dst, const void* src) {
    asm volatile("cp.async.cg.shared.global [%0], [%1], 16;" :: "r"(dst), "l"(src) : "memory");
}
__device__ __forceinline__ float fast_rcp(float x) {
    float r; asm("rcp.approx.f32 %0, %1;" : "=f"(r) : "f"(x)); return r;
}
__device__ __forceinline__ float fast_sigmoid(float x) {
    return fast_rcp(1.0f + __expf(-x));
}
__device__ __forceinline__ float fast_tanh(float x) {
    float r; asm("tanh.approx.f32 %0, %1;" : "=f"(r) : "f"(x)); return r;
}
// split central barrier (R10 mechanism): counter + single flag word per (group, phase)
__device__ __forceinline__ void bar_arrive(int slot, unsigned tag) {
    unsigned v;
    asm volatile("atom.add.acq_rel.gpu.global.u32 %0, [%1], 1;"
                 : "=r"(v) : "l"(&g_cnt[slot]) : "memory");
    if (v + 1u == tag * 8u) {
        asm volatile("st.release.gpu.global.u32 [%0], %1;"
                     :: "l"(&g_flag[slot]), "r"(tag) : "memory");
    }
}
__device__ __forceinline__ void bar_poll(int slot, unsigned tag) {
    unsigned f;
    do {
        asm volatile("ld.acquire.gpu.global.u32 %0, [%1];"
                     : "=r"(f) : "l"(&g_flag[slot]) : "memory");
    } while (f < tag);
}

// ---------------- K0: per-launch init ----------------
__global__ void k0_init(const float* __restrict__ bih0, const float* __restrict__ bhh0,
                        const float* __restrict__ bih1, const float* __restrict__ bhh1) {
    int i = blockIdx.x * blockDim.x + threadIdx.x;   // 32768 = 16*2048
    g_bias0[i] = bih0[i] + bhh0[i];
    g_bias1[i] = bih1[i] + bhh1[i];
    if (i < 32) { g_cnt[i] = 0u; g_flag[i] = 0u; }
}

// ---------------- K1: pack/transpose recurrent weights to fp16 [k][row] ----------------
// grid (8 ktile, 8 rank, 32 = m*16+b), 256 threads; tile = 64 k x 256 rows
__global__ void k1_pack(const float* __restrict__ whh0, const float* __restrict__ wih1,
                        const float* __restrict__ whh1) {
    __shared__ __align__(16) __half sm[64 * 264];
    int kt = blockIdx.x, r = blockIdx.y;
    int mb = blockIdx.z; int m = mb >> 4, b = mb & 15;
    int tid = threadIdx.x;
    int grow = ((tid >> 6) << 9) + (r << 6) + (tid & 63);
    int k0 = kt * 64;
    const float* s0 = (m == 0 ? whh0 : wih1) + ((size_t)(b * 2048 + grow) * 512 + k0);
    const float* s1 = whh1 + ((size_t)(b * 2048 + grow) * 512 + k0);
#pragma unroll
    for (int q = 0; q < 16; q++) {
        float4 v = *(const float4*)(s0 + q * 4);
        if (m) {
            float4 u = *(const float4*)(s1 + q * 4);
            v.x += u.x; v.y += u.y; v.z += u.z; v.w += u.w;
        }
        sm[(q * 4 + 0) * 264 + tid] = __float2half(v.x);
        sm[(q * 4 + 1) * 264 + tid] = __float2half(v.y);
        sm[(q * 4 + 2) * 264 + tid] = __float2half(v.z);
        sm[(q * 4 + 3) * 264 + tid] = __float2half(v.w);
    }
    __syncthreads();
    __half* out = &g_warr[(((size_t)mb) * 8u + r) * 512u * 256u + (size_t)k0 * 256u];
    int kk = tid >> 2, rb = (tid & 3) * 64;
    const uint4* src = (const uint4*)(sm + kk * 264 + rb);
    uint4* dst = (uint4*)(out + kk * 256 + rb);
#pragma unroll
    for (int q = 0; q < 8; q++) dst[q] = src[q];
}

// ---------------- K2: precompute gi0[b][t][row] = wih0@x_t + bias0 ----------------
__global__ void k2_gemm(const float* __restrict__ wih0, const float* __restrict__ x) {
    __shared__ float As[64][17];
    __shared__ float Bs[16][65];
    int rt = blockIdx.x, tt = blockIdx.y, b = blockIdx.z;
    int row0 = rt * 64, t0 = tt * 64;
    int tid = threadIdx.x;
    int lm = tid >> 2, kq = tid & 3;
    const float* Ap = wih0 + ((size_t)(b * 2048 + row0 + lm) * 512 + kq * 4);
    const float* Bp = x + ((size_t)(b * 256 + t0 + lm) * 512 + kq * 4);
    int ty = tid >> 4, tx = tid & 15;
    float C[4][4];
#pragma unroll
    for (int i = 0; i < 4; i++)
#pragma unroll
        for (int j = 0; j < 4; j++) C[i][j] = 0.f;

    for (int kc = 0; kc < 512; kc += 16) {
        float4 a4 = *(const float4*)(Ap + kc);
        float4 b4 = *(const float4*)(Bp + kc);
        As[lm][kq * 4 + 0] = a4.x; As[lm][kq * 4 + 1] = a4.y;
        As[lm][kq * 4 + 2] = a4.z; As[lm][kq * 4 + 3] = a4.w;
        Bs[kq * 4 + 0][lm] = b4.x; Bs[kq * 4 + 1][lm] = b4.y;
        Bs[kq * 4 + 2][lm] = b4.z; Bs[kq * 4 + 3][lm] = b4.w;
        __syncthreads();
#pragma unroll
        for (int kk = 0; kk < 16; kk++) {
            float a[4], bb[4];
#pragma unroll
            for (int i = 0; i < 4; i++) a[i] = As[ty * 4 + i][kk];
#pragma unroll
            for (int j = 0; j < 4; j++) bb[j] = Bs[kk][tx * 4 + j];
#pragma unroll
            for (int i = 0; i < 4; i++)
#pragma unroll
                for (int j = 0; j < 4; j++) C[i][j] += a[i] * bb[j];
        }
        __syncthreads();
    }
    float4 bias = *(const float4*)&g_bias0[b * 2048 + row0 + ty * 4];
#pragma unroll
    for (int j = 0; j < 4; j++) {
        float4 vo;
        vo.x = C[0][j] + bias.x; vo.y = C[1][j] + bias.y;
        vo.z = C[2][j] + bias.z; vo.w = C[3][j] + bias.w;
        *(float4*)&g_gi0[((size_t)(b * 256 + t0 + tx * 4 + j)) * 2048 + row0 + ty * 4] = vo;
    }
}

// ---------------- K3: persistent recurrent kernel (R10 skeleton + serial-path cuts) ----------------
// 128 CTAs x 256 threads. group g = batch, rank r owns h[64r..64r+64) + its 256 gate rows.
// Weight stream via 6-slot cp.async ring (consume-then-refill). Sync: R10 central cnt+flag
// barrier, split arrive/poll fused into warp 0 with smem broadcast of the gathered stats.
struct K3S {
    __half wring[RD * 64 * 256];   // 196608 B: RD chunk slots, [k64][row256]
    float h_s[512];
    float red[8][256];
    float act_s[256];
    float wpart[8][2];
    float2 stats_s[32];            // broadcast of all 8 ranks x 4 gates
    float gwf[1024], gbf[1024];    // LN params, both layers
    float bias1_s[256];
};

__global__ void __launch_bounds__(256, 1)
k3_lstm(const float* __restrict__ ln_w, const float* __restrict__ ln_b, float* __restrict__ y) {
    extern __shared__ __align__(16) unsigned char sraw[];
    K3S* S = (K3S*)sraw;

    int bid = blockIdx.x;
    int g = bid >> 3, r = bid & 7;
    int tid = threadIdx.x, warp = tid >> 5, lane = tid & 31;
    int gate = tid >> 6, jl = tid & 63;
    int slotA = g * 2, slotB = g * 2 + 1;

    const uint4* Wl[2];
    Wl[0] = (const uint4*)&g_warr[(((size_t)(0 * 16 + g)) * 8u + r) * 512u * 256u];
    Wl[1] = (const uint4*)&g_warr[(((size_t)(1 * 16 + g)) * 8u + r) * 512u * 256u];
    uint32_t wring_a = smem_u32(S->wring) + (uint32_t)(warp * 256 + lane) * 16u;

    int iss_it = 0, iss_c = 0, iss_slot = 0;
#define ISSUE_CHUNK() do {                                                          \
        if (iss_it < 512) {                                                         \
            const uint4* _src = Wl[iss_it & 1] + (size_t)((iss_c * 64 + warp * 8) * 32 + lane); \
            uint32_t _dst = wring_a + (uint32_t)(iss_slot * 32768);                 \
            _Pragma("unroll")                                                       \
            for (int _i = 0; _i < 8; _i++) cpa16(_dst + _i * 512u, _src + _i * 32); \
        }                                                                           \
        asm volatile("cp.async.commit_group;" ::: "memory");                        \
        if (++iss_c == 8) { iss_c = 0; iss_it++; }                                  \
        if (++iss_slot == RD) iss_slot = 0;                                         \
    } while (0)

    // prologue: fill the whole ring (6 chunks ahead), init state
    ISSUE_CHUNK(); ISSUE_CHUNK(); ISSUE_CHUNK();
    ISSUE_CHUNK(); ISSUE_CHUNK(); ISSUE_CHUNK();
    S->h_s[tid] = 0.f; S->h_s[tid + 256] = 0.f;
    for (int i = tid; i < 1024; i += 256) { S->gwf[i] = ln_w[i]; S->gbf[i] = ln_b[i]; }
    S->bias1_s[tid] = g_bias1[g * 2048 + (gate << 9) + (r << 6) + jl];
    __syncthreads();

    float c_r = 0.f;           // cell state: thread tid<64 owns j = r*64 + tid
    unsigned tag = 0;
    int comp_slot = 0;

    for (int t = 0; t < 256; t++) {
        const float* gi0_t = &g_gi0[((size_t)(g * 256 + t)) * 2048];
        for (int l = 0; l < 2; l++) {
            tag++;

            // ---- per-row additive term (issue load early) ----
            int rowg = (gate << 9) + (r << 6) + jl;
            float gin = l ? S->bias1_s[tid] : __ldcg(gi0_t + rowg);

            // ---- matvec via smem ring: 8 chunks; consume slot, then refill it ----
            float acc[8];
#pragma unroll
            for (int i = 0; i < 8; i++) acc[i] = 0.f;
#pragma unroll 1
            for (int c = 0; c < 8; c++) {
                asm volatile("cp.async.wait_group 5;" ::: "memory");
                const uint4* wp = (const uint4*)S->wring + comp_slot * 2048 + warp * 256 + lane;
                const float* hp_s = &S->h_s[c * 64 + warp * 8];
#pragma unroll
                for (int i = 0; i < 8; i++) {
                    uint4 w4 = wp[i * 32];
                    float hk = hp_s[i];
                    const __half2* hp = (const __half2*)&w4;
                    float2 f0 = __half22float2(hp[0]);
                    float2 f1 = __half22float2(hp[1]);
                    float2 f2 = __half22float2(hp[2]);
                    float2 f3 = __half22float2(hp[3]);
                    acc[0] += hk * f0.x; acc[1] += hk * f0.y;
                    acc[2] += hk * f1.x; acc[3] += hk * f1.y;
                    acc[4] += hk * f2.x; acc[5] += hk * f2.y;
                    acc[6] += hk * f3.x; acc[7] += hk * f3.y;
                }
                ISSUE_CHUNK();                   // refill slot just consumed
                if (++comp_slot == RD) comp_slot = 0;
            }
            *(float4*)&S->red[warp][lane * 8]     = make_float4(acc[0], acc[1], acc[2], acc[3]);
            *(float4*)&S->red[warp][lane * 8 + 4] = make_float4(acc[4], acc[5], acc[6], acc[7]);
            __syncthreads();
            float v = gin;
#pragma unroll
            for (int w = 0; w < 8; w++) v += S->red[w][tid];

            // ---- gate LN partial stats (2 warps per gate) ----
            float s = v, q = v * v;
#pragma unroll
            for (int o = 16; o > 0; o >>= 1) {
                s += __shfl_xor_sync(0xffffffffu, s, o);
                q += __shfl_xor_sync(0xffffffffu, q, o);
            }
            if (lane == 0) { S->wpart[warp][0] = s; S->wpart[warp][1] = q; }
            __syncthreads();

            // ---- X1: publish own partials, arrive, poll, broadcast-load (warp 0 only) ----
            if (warp == 0) {
                if (lane < 4) {
                    float2 p;
                    p.x = S->wpart[2 * lane][0] + S->wpart[2 * lane + 1][0];
                    p.y = S->wpart[2 * lane][1] + S->wpart[2 * lane + 1][1];
                    __stcg(&g_stat[(g * 8 + r) * 4 + lane], p);
                }
                __syncwarp();
                if (lane == 0) {
                    bar_arrive(slotA, tag);
                    bar_poll(slotA, tag);
                }
                __syncwarp();
                S->stats_s[lane] = __ldcg(&g_stat[g * 32 + lane]);   // [rank*4+gate]
            }
            __syncthreads();

            // ---- finalize gate LN + activation (stats from smem broadcast) ----
            {
                float Ssum = 0.f, Q = 0.f;
#pragma unroll
                for (int rr = 0; rr < 8; rr++) {
                    float2 p = S->stats_s[rr * 4 + gate];
                    Ssum += p.x; Q += p.y;
                }
                float mean = Ssum * (1.f / 512.f);
                float var  = Q * (1.f / 512.f) - mean * mean;
                float rstd = rsqrtf(var + EPS);
                float xn = (v - mean) * rstd * S->gwf[(l << 9) + (r << 6) + jl]
                         + S->gbf[(l << 9) + (r << 6) + jl];
                S->act_s[tid] = (gate == 2) ? fast_tanh(xn) : fast_sigmoid(xn);
            }
            __syncthreads();

            // ---- c update + X2 publish (c, o) for own j-slice ----
            if (tid < 64) {
                c_r = S->act_s[64 + tid] * c_r + S->act_s[tid] * S->act_s[128 + tid];
                __stcg(&g_co[g * 512 + r * 64 + tid], make_float2(c_r, S->act_s[192 + tid]));
            }
            __syncthreads();                       // all (c,o) stores issued
            if (tid == 0) {
                bar_arrive(slotB, tag);
                bar_poll(slotB, tag);
            }
            __syncthreads();

            // ---- merged: every rank computes global c-stats + full h locally ----
            float2 p0 = __ldcg(&g_co[g * 512 + tid]);         // j = tid
            float2 p1 = __ldcg(&g_co[g * 512 + 256 + tid]);   // j = tid + 256
            {
                float s2 = p0.x + p1.x, q2 = p0.x * p0.x + p1.x * p1.x;
#pragma unroll
                for (int o = 16; o > 0; o >>= 1) {
                    s2 += __shfl_xor_sync(0xffffffffu, s2, o);
                    q2 += __shfl_xor_sync(0xffffffffu, q2, o);
                }
                if (lane == 0) { S->wpart[warp][0] = s2; S->wpart[warp][1] = q2; }
            }
            __syncthreads();
            {
                float Sc = 0.f, Qc = 0.f;
#pragma unroll
                for (int w = 0; w < 8; w++) { Sc += S->wpart[w][0]; Qc += S->wpart[w][1]; }
                float mean = Sc * (1.f / 512.f);
                float var  = Qc * (1.f / 512.f) - mean * mean;
                float rstd = rsqrtf(var + EPS);
                int j0 = tid, j1 = tid + 256;
                float h0 = p0.y * fast_tanh((p0.x - mean) * rstd * S->gwf[(l << 9) + j0] + S->gbf[(l << 9) + j0]);
                float h1 = p1.y * fast_tanh((p1.x - mean) * rstd * S->gwf[(l << 9) + j1] + S->gbf[(l << 9) + j1]);
                S->h_s[j0] = h0;
                S->h_s[j1] = h1;
                if (l == 1) {
                    float* yt = &y[((size_t)(g * 256 + t)) * 512];
                    if ((j0 >> 6) == r) yt[j0] = h0;
                    if ((j1 >> 6) == r) yt[j1] = h1;
                }
            }
            __syncthreads();
        }
    }
#undef ISSUE_CHUNK
}

// ---------------- launcher ----------------
extern "C" void kernel_launch(void* const* d_in, const int* in_sizes, int n_in,
                              void* d_out, int out_size) {
    (void)in_sizes; (void)n_in; (void)out_size;
    const float* x    = (const float*)d_in[0];
    const float* wih0 = (const float*)d_in[1];
    const float* whh0 = (const float*)d_in[2];
    const float* bih0 = (const float*)d_in[3];
    const float* bhh0 = (const float*)d_in[4];
    const float* wih1 = (const float*)d_in[5];
    const float* whh1 = (const float*)d_in[6];
    const float* bih1 = (const float*)d_in[7];
    const float* bhh1 = (const float*)d_in[8];
    const float* ln_w = (const float*)d_in[9];
    const float* ln_b = (const float*)d_in[10];
    float* y = (float*)d_out;

    cudaFuncSetAttribute(k3_lstm, cudaFuncAttributeMaxDynamicSharedMemorySize,
                         (int)sizeof(K3S));

    k0_init<<<128, 256>>>(bih0, bhh0, bih1, bhh1);
    k1_pack<<<dim3(8, 8, 32), 256>>>(whh0, wih1, whh1);
    k2_gemm<<<dim3(32, 4, 16), 256>>>(wih0, x);
    k3_lstm<<<128, 256, sizeof(K3S)>>>(ln_w, ln_b, y);
}

// round 17
// speedup vs baseline: 2.6500x; 1.0969x over previous
#include <cuda_runtime.h>
#include <cuda_fp16.h>
#include <cstdint>

#define EPS 1e-5f
#define RD 6            // smem ring depth (chunks of 32KB)

// ---------------- device globals (scratch; no allocations allowed) ----------------
// packed recurrent weights: [m][b][r][k=512][rowlocal=256] fp16 ; m=0: whh0, m=1: wih1+whh1
__device__ __half g_warr[2u * 16u * 8u * 512u * 256u];                 // 67.1 MB
__device__ float g_gi0[16u * 256u * 2048u];                            // 33.5 MB: wih0@x + bias0
__device__ float g_bias0[16u * 2048u];
__device__ float g_bias1[16u * 2048u];
__device__ __half g_wh0[16u * 2048u * 512u];                           // 33.5 MB fp16 wih0
__device__ __half g_xh[16u * 256u * 512u];                             // 4.2 MB fp16 x
__device__ float2 g_part[16u * 8u * 4u];                               // gate stats: [b][rank][gate]
__device__ float2 g_co[16u * 512u];                                    // (c, o) pairs: [b][j]
__device__ unsigned g_cnt[32];
__device__ unsigned g_flag[32];

// ---------------- helpers ----------------
__device__ __forceinline__ uint32_t smem_u32(const void* p) {
    uint32_t a;
    asm("{ .reg .u64 t; cvta.to.shared.u64 t, %1; cvt.u32.u64 %0, t; }" : "=r"(a) : "l"(p));
    return a;
}
__device__ __forceinline__ void cpa16(uint32_t dst, const void* src) {
    asm volatile("cp.async.cg.shared.global [%0], [%1], 16;" :: "r"(dst), "l"(src) : "memory");
}
__device__ __forceinline__ float fast_rcp(float x) {
    float r; asm("rcp.approx.f32 %0, %1;" : "=f"(r) : "f"(x)); return r;
}
__device__ __forceinline__ float fast_sigmoid(float x) {
    return fast_rcp(1.0f + __expf(-x));
}
__device__ __forceinline__ float fast_tanh(float x) {
    float r; asm("tanh.approx.f32 %0, %1;" : "=f"(r) : "f"(x)); return r;
}

// group barrier among the 8 CTAs of group g via scoped atomics (R10 mechanism).
__device__ __forceinline__ void group_barrier(int g, unsigned target) {
    __syncthreads();
    if (threadIdx.x == 0) {
        unsigned v;
        asm volatile("atom.add.acq_rel.gpu.global.u32 %0, [%1], 1;"
                     : "=r"(v) : "l"(&g_cnt[g]) : "memory");
        if (v + 1u == target * 8u) {
            asm volatile("st.release.gpu.global.u32 [%0], %1;"
                         :: "l"(&g_flag[g]), "r"(target) : "memory");
        } else {
            unsigned f;
            do {
                asm volatile("ld.acquire.gpu.global.u32 %0, [%1];"
                             : "=r"(f) : "l"(&g_flag[g]) : "memory");
            } while (f < target);
        }
    }
    __syncthreads();
}

// mma / ldmatrix wrappers
__device__ __forceinline__ void mma16816(float* c, const uint32_t* a, const uint32_t* b) {
    asm volatile(
        "mma.sync.aligned.m16n8k16.row.col.f32.f16.f16.f32 "
        "{%0,%1,%2,%3}, {%4,%5,%6,%7}, {%8,%9}, {%0,%1,%2,%3};"
        : "+f"(c[0]), "+f"(c[1]), "+f"(c[2]), "+f"(c[3])
        : "r"(a[0]), "r"(a[1]), "r"(a[2]), "r"(a[3]), "r"(b[0]), "r"(b[1]));
}
__device__ __forceinline__ void ldsm_x4(uint32_t* r, uint32_t addr) {
    asm volatile("ldmatrix.sync.aligned.m8n8.x4.shared.b16 {%0,%1,%2,%3}, [%4];"
        : "=r"(r[0]), "=r"(r[1]), "=r"(r[2]), "=r"(r[3]) : "r"(addr));
}
__device__ __forceinline__ void ldsm_x2(uint32_t* r, uint32_t addr) {
    asm volatile("ldmatrix.sync.aligned.m8n8.x2.shared.b16 {%0,%1}, [%2];"
        : "=r"(r[0]), "=r"(r[1]) : "r"(addr));
}

// ---------------- K0: per-launch init ----------------
__global__ void k0_init(const float* __restrict__ bih0, const float* __restrict__ bhh0,
                        const float* __restrict__ bih1, const float* __restrict__ bhh1) {
    int i = blockIdx.x * blockDim.x + threadIdx.x;   // 32768 = 16*2048
    g_bias0[i] = bih0[i] + bhh0[i];
    g_bias1[i] = bih1[i] + bhh1[i];
    if (i < 32) { g_cnt[i] = 0u; g_flag[i] = 0u; }
}

// ---------------- K0b: fp16 conversion of x and wih0 ----------------
__global__ void k0b_cvt(const float* __restrict__ x, const float* __restrict__ wih0) {
    int i = blockIdx.x * blockDim.x + threadIdx.x;   // 16,777,216
    g_wh0[i] = __float2half(wih0[i]);
    if (i < 16 * 256 * 512) g_xh[i] = __float2half(x[i]);
}

// ---------------- K1: pack/transpose recurrent weights to fp16 [k][row] ----------------
// grid (8 ktile, 8 rank, 32 = m*16+b), 256 threads; tile = 64 k x 256 rows
__global__ void k1_pack(const float* __restrict__ whh0, const float* __restrict__ wih1,
                        const float* __restrict__ whh1) {
    __shared__ __align__(16) __half sm[64 * 264];
    int kt = blockIdx.x, r = blockIdx.y;
    int mb = blockIdx.z; int m = mb >> 4, b = mb & 15;
    int tid = threadIdx.x;
    int grow = ((tid >> 6) << 9) + (r << 6) + (tid & 63);
    int k0 = kt * 64;
    const float* s0 = (m == 0 ? whh0 : wih1) + ((size_t)(b * 2048 + grow) * 512 + k0);
    const float* s1 = whh1 + ((size_t)(b * 2048 + grow) * 512 + k0);
#pragma unroll
    for (int q = 0; q < 16; q++) {
        float4 v = *(const float4*)(s0 + q * 4);
        if (m) {
            float4 u = *(const float4*)(s1 + q * 4);
            v.x += u.x; v.y += u.y; v.z += u.z; v.w += u.w;
        }
        sm[(q * 4 + 0) * 264 + tid] = __float2half(v.x);
        sm[(q * 4 + 1) * 264 + tid] = __float2half(v.y);
        sm[(q * 4 + 2) * 264 + tid] = __float2half(v.z);
        sm[(q * 4 + 3) * 264 + tid] = __float2half(v.w);
    }
    __syncthreads();
    __half* out = &g_warr[(((size_t)mb) * 8u + r) * 512u * 256u + (size_t)k0 * 256u];
    int kk = tid >> 2, rb = (tid & 3) * 64;
    const uint4* src = (const uint4*)(sm + kk * 264 + rb);
    uint4* dst = (uint4*)(out + kk * 256 + rb);
#pragma unroll
    for (int q = 0; q < 8; q++) dst[q] = src[q];
}

// ---------------- K2: tensor-core GEMM: gi0[b][t][row] = X[t,:]·W[row,:]^T + bias0 ----------------
// CTA tile: M=64 (t) x N=128 (row), K-step 16, double-buffered cp.async.
// grid (16 rowtile, 4 ttile, 16 b), 256 threads = 8 warps (2 M x 4 N), warp tile 32x32.
__global__ void __launch_bounds__(256) k2_tc() {
    __shared__ __align__(16) __half Xs[2][64 * 24];     // stride 24 halfs (48B)
    __shared__ __align__(16) __half Ws[2][128 * 24];
    int rt = blockIdx.x, tt = blockIdx.y, b = blockIdx.z;
    int row0 = rt * 128, t0 = tt * 64;
    int tid = threadIdx.x, warp = tid >> 5, lane = tid & 31;
    int wm = warp >> 2, wn = warp & 3;

    const __half* Xg = g_xh + ((size_t)(b * 256 + t0)) * 512;
    const __half* Wg = g_wh0 + ((size_t)(b * 2048 + row0)) * 512;
    uint32_t xs_u = smem_u32(Xs), ws_u = smem_u32(Ws);

    int lrow = tid >> 1, lseg = tid & 1;

#define K2_LOAD(st, ks) do {                                                        \
        int _k0 = (ks) * 16 + lseg * 8;                                             \
        if (tid < 128)                                                              \
            cpa16(xs_u + (uint32_t)(((st) * 64 * 24 + lrow * 24 + lseg * 8) * 2),   \
                  Xg + lrow * 512 + _k0);                                           \
        cpa16(ws_u + (uint32_t)(((st) * 128 * 24 + lrow * 24 + lseg * 8) * 2),      \
              Wg + lrow * 512 + _k0);                                               \
        asm volatile("cp.async.commit_group;" ::: "memory");                        \
    } while (0)

    float acc[2][4][4];
#pragma unroll
    for (int i = 0; i < 2; i++)
#pragma unroll
        for (int j = 0; j < 4; j++)
#pragma unroll
            for (int q = 0; q < 4; q++) acc[i][j][q] = 0.f;

    K2_LOAD(0, 0);
#pragma unroll 1
    for (int ks = 0; ks < 32; ks++) {
        int st = ks & 1;
        if (ks < 31) {
            K2_LOAD(st ^ 1, ks + 1);
            asm volatile("cp.async.wait_group 1;" ::: "memory");
        } else {
            asm volatile("cp.async.wait_group 0;" ::: "memory");
        }
        __syncthreads();

        uint32_t a[2][4], bf[4][2];
        int arow = wm * 32 + (lane & 15);
        int akoff = (lane >> 4) * 8;
#pragma unroll
        for (int mm = 0; mm < 2; mm++)
            ldsm_x4(a[mm], xs_u + (uint32_t)(((st * 64 + arow + mm * 16) * 24 + akoff) * 2));
        int brow = wn * 32 + (lane & 7);
        int bkoff = ((lane >> 3) & 1) * 8;
#pragma unroll
        for (int nn = 0; nn < 4; nn++)
            ldsm_x2(bf[nn], ws_u + (uint32_t)(((st * 128 + brow + nn * 8) * 24 + bkoff) * 2));
#pragma unroll
        for (int mm = 0; mm < 2; mm++)
#pragma unroll
            for (int nn = 0; nn < 4; nn++)
                mma16816(acc[mm][nn], a[mm], bf[nn]);
        __syncthreads();
    }
#undef K2_LOAD

    // epilogue: c frag (m16n8): c0,c1 -> (t=g, row=2q,2q+1); c2,c3 -> t=g+8
#pragma unroll
    for (int mm = 0; mm < 2; mm++)
#pragma unroll
        for (int nn = 0; nn < 4; nn++) {
            int t = t0 + wm * 32 + mm * 16 + (lane >> 2);
            int row = row0 + wn * 32 + nn * 8 + (lane & 3) * 2;
            float2 bia = *(const float2*)&g_bias0[b * 2048 + row];
            float* d0 = &g_gi0[((size_t)(b * 256 + t)) * 2048 + row];
            *(float2*)d0 = make_float2(acc[mm][nn][0] + bia.x, acc[mm][nn][1] + bia.y);
            float* d1 = &g_gi0[((size_t)(b * 256 + t + 8)) * 2048 + row];
            *(float2*)d1 = make_float2(acc[mm][nn][2] + bia.x, acc[mm][nn][3] + bia.y);
        }
}

// ---------------- K3: persistent recurrent kernel (R10 exact + MUFU tanh) ----------------
// 128 CTAs x 256 threads. group g = batch, rank r owns h[64r..64r+64) + its 256 gate rows.
struct K3S {
    __half wring[RD * 64 * 256];   // 196608 B: RD chunk slots, [k64][row256]
    float h_s[512];
    float red[8][256];
    float act_s[256];
    float wpart[8][2];
    float gwf[1024], gbf[1024];    // LN params, both layers
    float bias1_s[256];
};

__global__ void __launch_bounds__(256, 1)
k3_lstm(const float* __restrict__ ln_w, const float* __restrict__ ln_b, float* __restrict__ y) {
    extern __shared__ __align__(16) unsigned char sraw[];
    K3S* S = (K3S*)sraw;

    int bid = blockIdx.x;
    int g = bid >> 3, r = bid & 7;
    int tid = threadIdx.x, warp = tid >> 5, lane = tid & 31;
    int gate = tid >> 6, jl = tid & 63;

    const uint4* Wl[2];
    Wl[0] = (const uint4*)&g_warr[(((size_t)(0 * 16 + g)) * 8u + r) * 512u * 256u];
    Wl[1] = (const uint4*)&g_warr[(((size_t)(1 * 16 + g)) * 8u + r) * 512u * 256u];
    uint32_t wring_a = smem_u32(S->wring) + (uint32_t)(warp * 256 + lane) * 16u;

    int iss_it = 0, iss_c = 0, iss_slot = 0;
#define ISSUE_CHUNK() do {                                                          \
        if (iss_it < 512) {                                                         \
            const uint4* _src = Wl[iss_it & 1] + (size_t)((iss_c * 64 + warp * 8) * 32 + lane); \
            uint32_t _dst = wring_a + (uint32_t)(iss_slot * 32768);                 \
            _Pragma("unroll")                                                       \
            for (int _i = 0; _i < 8; _i++) cpa16(_dst + _i * 512u, _src + _i * 32); \
        }                                                                           \
        asm volatile("cp.async.commit_group;" ::: "memory");                        \
        if (++iss_c == 8) { iss_c = 0; iss_it++; }                                  \
        if (++iss_slot == RD) iss_slot = 0;                                         \
    } while (0)

    // prologue: start the pipeline (chunks 0..4), init state
    ISSUE_CHUNK(); ISSUE_CHUNK(); ISSUE_CHUNK(); ISSUE_CHUNK(); ISSUE_CHUNK();
    S->h_s[tid] = 0.f; S->h_s[tid + 256] = 0.f;
    for (int i = tid; i < 1024; i += 256) { S->gwf[i] = ln_w[i]; S->gbf[i] = ln_b[i]; }
    S->bias1_s[tid] = g_bias1[g * 2048 + (gate << 9) + (r << 6) + jl];
    __syncthreads();

    float c_r = 0.f;           // cell state: thread tid<64 owns j = r*64 + tid
    unsigned bar = 0;
    int comp_slot = 0;

    for (int t = 0; t < 256; t++) {
        const float* gi0_t = &g_gi0[((size_t)(g * 256 + t)) * 2048];
        for (int l = 0; l < 2; l++) {
            // ---- per-row additive term (issue load early) ----
            int rowg = (gate << 9) + (r << 6) + jl;
            float gin = l ? S->bias1_s[tid] : __ldcg(gi0_t + rowg);

            // ---- matvec via smem ring: 8 chunks; issue-ahead then wait ----
            float acc[8];
#pragma unroll
            for (int i = 0; i < 8; i++) acc[i] = 0.f;
#pragma unroll 1
            for (int c = 0; c < 8; c++) {
                ISSUE_CHUNK();
                asm volatile("cp.async.wait_group 5;" ::: "memory");
                const uint4* wp = (const uint4*)S->wring + comp_slot * 2048 + warp * 256 + lane;
                const float* hp_s = &S->h_s[c * 64 + warp * 8];
#pragma unroll
                for (int i = 0; i < 8; i++) {
                    uint4 w4 = wp[i * 32];
                    float hk = hp_s[i];
                    const __half2* hp = (const __half2*)&w4;
                    float2 f0 = __half22float2(hp[0]);
                    float2 f1 = __half22float2(hp[1]);
                    float2 f2 = __half22float2(hp[2]);
                    float2 f3 = __half22float2(hp[3]);
                    acc[0] += hk * f0.x; acc[1] += hk * f0.y;
                    acc[2] += hk * f1.x; acc[3] += hk * f1.y;
                    acc[4] += hk * f2.x; acc[5] += hk * f2.y;
                    acc[6] += hk * f3.x; acc[7] += hk * f3.y;
                }
                if (++comp_slot == RD) comp_slot = 0;
            }
            *(float4*)&S->red[warp][lane * 8]     = make_float4(acc[0], acc[1], acc[2], acc[3]);
            *(float4*)&S->red[warp][lane * 8 + 4] = make_float4(acc[4], acc[5], acc[6], acc[7]);
            __syncthreads();
            float v = gin;
#pragma unroll
            for (int w = 0; w < 8; w++) v += S->red[w][tid];

            // ---- gate LN partial stats (2 warps per gate) ----
            float s = v, q = v * v;
#pragma unroll
            for (int o = 16; o > 0; o >>= 1) {
                s += __shfl_xor_sync(0xffffffffu, s, o);
                q += __shfl_xor_sync(0xffffffffu, q, o);
            }
            if (lane == 0) { S->wpart[warp][0] = s; S->wpart[warp][1] = q; }
            __syncthreads();
            if (tid < 4) {
                float2 p;
                p.x = S->wpart[2 * tid][0] + S->wpart[2 * tid + 1][0];
                p.y = S->wpart[2 * tid][1] + S->wpart[2 * tid + 1][1];
                __stcg(&g_part[(g * 8 + r) * 4 + tid], p);
            }
            group_barrier(g, ++bar);          // X1: gate partials visible

            // ---- finalize gate LN + activation ----
            {
                float Ssum = 0.f, Q = 0.f;
#pragma unroll
                for (int rr = 0; rr < 8; rr++) {
                    float2 p = __ldcg(&g_part[(g * 8 + rr) * 4 + gate]);
                    Ssum += p.x; Q += p.y;
                }
                float mean = Ssum * (1.f / 512.f);
                float var  = Q * (1.f / 512.f) - mean * mean;
                float rstd = rsqrtf(var + EPS);
                float xn = (v - mean) * rstd * S->gwf[(l << 9) + (r << 6) + jl]
                         + S->gbf[(l << 9) + (r << 6) + jl];
                S->act_s[tid] = (gate == 2) ? fast_tanh(xn) : fast_sigmoid(xn);
            }
            __syncthreads();

            // ---- c update + publish (c, o) for own j-slice ----
            if (tid < 64) {
                c_r = S->act_s[64 + tid] * c_r + S->act_s[tid] * S->act_s[128 + tid];
                __stcg(&g_co[g * 512 + r * 64 + tid], make_float2(c_r, S->act_s[192 + tid]));
            }
            group_barrier(g, ++bar);          // X2: (c,o) pairs visible

            // ---- merged: every rank computes global c-stats + full h locally ----
            float2 p0 = __ldcg(&g_co[g * 512 + tid]);         // j = tid
            float2 p1 = __ldcg(&g_co[g * 512 + 256 + tid]);   // j = tid + 256
            {
                float s2 = p0.x + p1.x, q2 = p0.x * p0.x + p1.x * p1.x;
#pragma unroll
                for (int o = 16; o > 0; o >>= 1) {
                    s2 += __shfl_xor_sync(0xffffffffu, s2, o);
                    q2 += __shfl_xor_sync(0xffffffffu, q2, o);
                }
                if (lane == 0) { S->wpart[warp][0] = s2; S->wpart[warp][1] = q2; }
            }
            __syncthreads();
            {
                float Sc = 0.f, Qc = 0.f;
#pragma unroll
                for (int w = 0; w < 8; w++) { Sc += S->wpart[w][0]; Qc += S->wpart[w][1]; }
                float mean = Sc * (1.f / 512.f);
                float var  = Qc * (1.f / 512.f) - mean * mean;
                float rstd = rsqrtf(var + EPS);
                int j0 = tid, j1 = tid + 256;
                float h0 = p0.y * fast_tanh((p0.x - mean) * rstd * S->gwf[(l << 9) + j0] + S->gbf[(l << 9) + j0]);
                float h1 = p1.y * fast_tanh((p1.x - mean) * rstd * S->gwf[(l << 9) + j1] + S->gbf[(l << 9) + j1]);
                S->h_s[j0] = h0;
                S->h_s[j1] = h1;
                if (l == 1) {
                    float* yt = &y[((size_t)(g * 256 + t)) * 512];
                    if ((j0 >> 6) == r) yt[j0] = h0;
                    if ((j1 >> 6) == r) yt[j1] = h1;
                }
            }
            __syncthreads();
        }
    }
#undef ISSUE_CHUNK
}

// ---------------- launcher ----------------
extern "C" void kernel_launch(void* const* d_in, const int* in_sizes, int n_in,
                              void* d_out, int out_size) {
    (void)in_sizes; (void)n_in; (void)out_size;
    const float* x    = (const float*)d_in[0];
    const float* wih0 = (const float*)d_in[1];
    const float* whh0 = (const float*)d_in[2];
    const float* bih0 = (const float*)d_in[3];
    const float* bhh0 = (const float*)d_in[4];
    const float* wih1 = (const float*)d_in[5];
    const float* whh1 = (const float*)d_in[6];
    const float* bih1 = (const float*)d_in[7];
    const float* bhh1 = (const float*)d_in[8];
    const float* ln_w = (const float*)d_in[9];
    const float* ln_b = (const float*)d_in[10];
    float* y = (float*)d_out;

    cudaFuncSetAttribute(k3_lstm, cudaFuncAttributeMaxDynamicSharedMemorySize,
                         (int)sizeof(K3S));

    k0_init<<<128, 256>>>(bih0, bhh0, bih1, bhh1);
    k0b_cvt<<<65536, 256>>>(x, wih0);
    k1_pack<<<dim3(8, 8, 32), 256>>>(whh0, wih1, whh1);
    k2_tc<<<dim3(16, 4, 16), 256>>>();
    k3_lstm<<<128, 256, sizeof(K3S)>>>(ln_w, ln_b, y);
}